// round 3
// baseline (speedup 1.0000x reference)
#include <cuda_runtime.h>

// LiveniumJoint: h stays in span{h0, a0n, a1n, a2n}; scalar coefficient
// recurrence. R3 = R2 (2 rows/warp halves, smem anchors, approx MUFU)
// + R1's next-row prefetch pipeline + streaming cache hints.

#define DD 768
#define VV 192            // float4 per row
#define KPL 12            // float4 per 16-lane half (192/16)
#define FULLMASK 0xffffffffu

__device__ float g_anch[3 * DD];  // normalized anchors
__device__ float g_G[9];          // Gram of normalized anchors

__device__ __forceinline__ float rcpa(float x) {
    float y; asm("rcp.approx.ftz.f32 %0,%1;" : "=f"(y) : "f"(x)); return y;
}
__device__ __forceinline__ float rsqa(float x) {
    float y; asm("rsqrt.approx.ftz.f32 %0,%1;" : "=f"(y) : "f"(x)); return y;
}
__device__ __forceinline__ float ex2a(float x) {
    float y; asm("ex2.approx.ftz.f32 %0,%1;" : "=f"(y) : "f"(x)); return y;
}
__device__ __forceinline__ float4 ldcs4(const float4* p) {
    float4 v;
    asm("ld.global.cs.v4.f32 {%0,%1,%2,%3}, [%4];"
        : "=f"(v.x), "=f"(v.y), "=f"(v.z), "=f"(v.w) : "l"(p));
    return v;
}
__device__ __forceinline__ void stcs4(float4* p, float4 v) {
    asm volatile("st.global.cs.v4.f32 [%0], {%1,%2,%3,%4};"
                 :: "l"(p), "f"(v.x), "f"(v.y), "f"(v.z), "f"(v.w));
}
#define LOG2E 1.4426950408889634f

// ---------------------------------------------------------------------------
// prep: normalize anchors, compute Gram. 1 block, 128 threads.
// ---------------------------------------------------------------------------
__global__ void liv_prep(const float* __restrict__ anchors) {
    __shared__ float s_an[3 * DD];
    int tid = threadIdx.x, w = tid >> 5, lane = tid & 31;
    if (w < 3) {
        float acc = 0.f;
        for (int k = lane; k < DD; k += 32) {
            float x = anchors[w * DD + k];
            acc = fmaf(x, x, acc);
        }
        #pragma unroll
        for (int o = 16; o; o >>= 1) acc += __shfl_xor_sync(FULLMASK, acc, o);
        float inv = 1.f / fmaxf(sqrtf(acc), 1e-12f);
        for (int k = lane; k < DD; k += 32) {
            float x = anchors[w * DD + k] * inv;
            s_an[w * DD + k] = x;
            g_anch[w * DD + k] = x;
        }
    }
    __syncthreads();
    if (w == 0) {
        float d00 = 0, d01 = 0, d02 = 0, d11 = 0, d12 = 0, d22 = 0;
        for (int k = lane; k < DD; k += 32) {
            float x0 = s_an[k], x1 = s_an[DD + k], x2 = s_an[2 * DD + k];
            d00 = fmaf(x0, x0, d00); d01 = fmaf(x0, x1, d01); d02 = fmaf(x0, x2, d02);
            d11 = fmaf(x1, x1, d11); d12 = fmaf(x1, x2, d12); d22 = fmaf(x2, x2, d22);
        }
        #pragma unroll
        for (int o = 16; o; o >>= 1) {
            d00 += __shfl_xor_sync(FULLMASK, d00, o);
            d01 += __shfl_xor_sync(FULLMASK, d01, o);
            d02 += __shfl_xor_sync(FULLMASK, d02, o);
            d11 += __shfl_xor_sync(FULLMASK, d11, o);
            d12 += __shfl_xor_sync(FULLMASK, d12, o);
            d22 += __shfl_xor_sync(FULLMASK, d22, o);
        }
        if (lane == 0) {
            g_G[0] = d00; g_G[1] = d01; g_G[2] = d02;
            g_G[3] = d11; g_G[4] = d12; g_G[5] = d22;
        }
    }
}

// ---------------------------------------------------------------------------
// main: 2 rows per warp (16-lane halves), smem anchors, 1-deep prefetch.
// ---------------------------------------------------------------------------
__global__ __launch_bounds__(128, 3)
void liv_main(const float* __restrict__ h0,
              float* __restrict__ out_h,
              float* __restrict__ out_al,
              int B) {
    __shared__ float4 s_an[3 * VV];   // 9 KB normalized anchors

    {
        const float4* av = (const float4*)g_anch;
        for (int i = threadIdx.x; i < 3 * VV; i += blockDim.x) s_an[i] = av[i];
    }
    const float G00 = g_G[0], G01 = g_G[1], G02 = g_G[2];
    const float G11 = g_G[3], G12 = g_G[4], G22 = g_G[5];
    __syncthreads();

    const int lane = threadIdx.x & 31;
    const int half = lane >> 4;
    const int hl = lane & 15;
    const int gw = (blockIdx.x * blockDim.x + threadIdx.x) >> 5;
    const int nwarps = (gridDim.x * blockDim.x) >> 5;
    const int npairs = (B + 1) >> 1;

    const float4* A0 = s_an;
    const float4* A1 = s_an + VV;
    const float4* A2 = s_an + 2 * VV;

    int pair = gw;
    if (pair >= npairs) return;

    // preload first pair's row (clamp row for odd-B safety)
    float4 h[KPL];
    {
        int row = pair * 2 + half; if (row >= B) row = B - 1;
        const float4* hp = (const float4*)h0 + (size_t)row * VV;
        #pragma unroll
        for (int k = 0; k < KPL; k++) h[k] = ldcs4(hp + k * 16 + hl);
    }

    while (pair < npairs) {
        const int row = pair * 2 + half;
        const int npair = pair + nwarps;

        // --- fused dots: N0=<h,h>, Tj=<h,anj> (per-half) ---
        float N0 = 0.f, T0 = 0.f, T1 = 0.f, T2 = 0.f;
        #pragma unroll
        for (int k = 0; k < KPL; k++) {
            const float4 a0 = A0[k * 16 + hl];
            const float4 a1 = A1[k * 16 + hl];
            const float4 a2 = A2[k * 16 + hl];
            N0 = fmaf(h[k].x, h[k].x, N0);
            N0 = fmaf(h[k].y, h[k].y, N0);
            N0 = fmaf(h[k].z, h[k].z, N0);
            N0 = fmaf(h[k].w, h[k].w, N0);
            T0 = fmaf(h[k].x, a0.x, T0);
            T0 = fmaf(h[k].y, a0.y, T0);
            T0 = fmaf(h[k].z, a0.z, T0);
            T0 = fmaf(h[k].w, a0.w, T0);
            T1 = fmaf(h[k].x, a1.x, T1);
            T1 = fmaf(h[k].y, a1.y, T1);
            T1 = fmaf(h[k].z, a1.z, T1);
            T1 = fmaf(h[k].w, a1.w, T1);
            T2 = fmaf(h[k].x, a2.x, T2);
            T2 = fmaf(h[k].y, a2.y, T2);
            T2 = fmaf(h[k].z, a2.z, T2);
            T2 = fmaf(h[k].w, a2.w, T2);
        }

        // --- prefetch next pair while reduce + scalar chain run ---
        float4 hn[KPL];
        if (npair < npairs) {
            int prow = npair * 2 + half; if (prow >= B) prow = B - 1;
            const float4* hp = (const float4*)h0 + (size_t)prow * VV;
            #pragma unroll
            for (int k = 0; k < KPL; k++) hn[k] = ldcs4(hp + k * 16 + hl);
        }

        // --- reduce within each 16-lane half ---
        #pragma unroll
        for (int o = 8; o; o >>= 1) {
            N0 += __shfl_xor_sync(FULLMASK, N0, o);
            T0 += __shfl_xor_sync(FULLMASK, T0, o);
            T1 += __shfl_xor_sync(FULLMASK, T1, o);
            T2 += __shfl_xor_sync(FULLMASK, T2, o);
        }

        // --- scalar recurrence (each half does its own row) ---
        float p = 1.f, q0 = 0.f, q1 = 0.f, q2 = 0.f;
        float al0 = 0.f, al1 = 0.f, al2 = 0.f;
        #pragma unroll
        for (int s = 0; s < 7; s++) {
            float s0 = fmaf(p, T0, fmaf(q0, G00, fmaf(q1, G01, q2 * G02)));
            float s1 = fmaf(p, T1, fmaf(q0, G01, fmaf(q1, G11, q2 * G12)));
            float s2 = fmaf(p, T2, fmaf(q0, G02, fmaf(q1, G12, q2 * G22)));
            float qT = fmaf(q0, T0, fmaf(q1, T1, q2 * T2));
            float n2 = fmaf(p, fmaf(p, N0, qT),
                            fmaf(q0, s0, fmaf(q1, s1, q2 * s2)));
            float inv = rsqa(fmaxf(n2, 1e-24f));
            float n = n2 * inv;   // sqrt(n2)
            al0 = s0 * inv; al1 = s1 * inv; al2 = s2 * inv;
            if (s == 6) break;    // final alignments only

            float l0 = 20.f * al0, l1 = 20.f * al1, l2 = 20.f * al2;
            float m = fmaxf(l0, fmaxf(l1, l2));
            float e0 = ex2a((l0 - m) * LOG2E);
            float e1 = ex2a((l1 - m) * LOG2E);
            float e2 = ex2a((l2 - m) * LOG2E);
            float invW = rcpa(e0 + e1 + e2);
            float w0 = e0 * invW, w1 = e1 * invW, w2 = e2 * invW;

            float c = fmaf(w0, al0, fmaf(w1, al1, w2 * al2));
            float beta = fmaf(-0.05f, c, 1.f);
            float delta = 0.05f * n;
            p *= beta;
            q0 = fmaf(beta, q0, delta * w0);
            q1 = fmaf(beta, q1, delta * w1);
            q2 = fmaf(beta, q2, delta * w2);

            float t2 = fmaf(w0 * w0, G00,
                       fmaf(w1 * w1, G11,
                       fmaf(w2 * w2, G22,
                       2.f * fmaf(w0 * w1, G01,
                             fmaf(w0 * w2, G02, w1 * w2 * G12)))));
            float n2b = n2 * fmaf(0.0025f, t2 - c * c, 1.f);
            if (n2b > 100.f) {
                float nb = n2b * rsqa(n2b);
                float g = 10.f * rcpa(nb + 1e-8f);
                p *= g; q0 *= g; q1 *= g; q2 *= g;
            }
        }

        // --- output: h_out = p*h0 + q0*a0 + q1*a1 + q2*a2 ---
        if (row < B) {
            float4* op = (float4*)out_h + (size_t)row * VV;
            #pragma unroll
            for (int k = 0; k < KPL; k++) {
                const float4 a0 = A0[k * 16 + hl];
                const float4 a1 = A1[k * 16 + hl];
                const float4 a2 = A2[k * 16 + hl];
                float4 o;
                o.x = fmaf(p, h[k].x, fmaf(q0, a0.x, fmaf(q1, a1.x, q2 * a2.x)));
                o.y = fmaf(p, h[k].y, fmaf(q0, a0.y, fmaf(q1, a1.y, q2 * a2.y)));
                o.z = fmaf(p, h[k].z, fmaf(q0, a0.z, fmaf(q1, a1.z, q2 * a2.z)));
                o.w = fmaf(p, h[k].w, fmaf(q0, a0.w, fmaf(q1, a1.w, q2 * a2.w)));
                stcs4(op + k * 16 + hl, o);
            }
            if (hl < 3) {
                float v = (hl == 0) ? al0 : ((hl == 1) ? al1 : al2);
                out_al[(size_t)row * 3 + hl] = v;
            }
        }

        #pragma unroll
        for (int k = 0; k < KPL; k++) h[k] = hn[k];
        pair = npair;
    }
}

// ---------------------------------------------------------------------------
extern "C" void kernel_launch(void* const* d_in, const int* in_sizes, int n_in,
                              void* d_out, int out_size) {
    const float* h0 = (const float*)d_in[0];       // [B, 768]
    const float* anchors = (const float*)d_in[1];  // [3, 768]
    const int B = in_sizes[0] / DD;

    float* out_h = (float*)d_out;                    // [B, 768]
    float* out_al = (float*)d_out + (size_t)B * DD;  // [B, 3]

    liv_prep<<<1, 128>>>(anchors);

    const int threads = 128;          // 4 warps/block
    int blocks = 2048;                // 8192 warps -> 4 pairs each
    int npairs = (B + 1) / 2;
    int total_warps = blocks * (threads / 32);
    if (total_warps > npairs) blocks = (npairs + 3) / 4;
    liv_main<<<blocks, threads>>>(h0, out_h, out_al, B);
}

// round 4
// speedup vs baseline: 1.8993x; 1.8993x over previous
#include <cuda_runtime.h>

// LiveniumJoint: h stays in span{h0, a0n, a1n, a2n}; scalar coefficient
// recurrence. R4: warp processes 4 rows per batch; anchors in registers
// (no smem in hot loop); ONE chain execution covers 4 rows (lane = row);
// branchless clip, no softmax max-subtraction, plain cache ops.

#define DD 768
#define VV 192            // float4 per row
#define KPL 6             // float4 per lane (192/32)
#define RB 4              // rows per warp-batch
#define FULLMASK 0xffffffffu

__device__ float g_anch[3 * DD];  // normalized anchors
__device__ float g_G[9];          // Gram of normalized anchors

__device__ __forceinline__ float rcpa(float x) {
    float y; asm("rcp.approx.ftz.f32 %0,%1;" : "=f"(y) : "f"(x)); return y;
}
__device__ __forceinline__ float rsqa(float x) {
    float y; asm("rsqrt.approx.ftz.f32 %0,%1;" : "=f"(y) : "f"(x)); return y;
}
__device__ __forceinline__ float ex2a(float x) {
    float y; asm("ex2.approx.ftz.f32 %0,%1;" : "=f"(y) : "f"(x)); return y;
}

// ---------------------------------------------------------------------------
// prep: normalize anchors, compute Gram. 1 block, 128 threads.
// ---------------------------------------------------------------------------
__global__ void liv_prep(const float* __restrict__ anchors) {
    __shared__ float s_an[3 * DD];
    int tid = threadIdx.x, w = tid >> 5, lane = tid & 31;
    if (w < 3) {
        float acc = 0.f;
        for (int k = lane; k < DD; k += 32) {
            float x = anchors[w * DD + k];
            acc = fmaf(x, x, acc);
        }
        #pragma unroll
        for (int o = 16; o; o >>= 1) acc += __shfl_xor_sync(FULLMASK, acc, o);
        float inv = 1.f / fmaxf(sqrtf(acc), 1e-12f);
        for (int k = lane; k < DD; k += 32) {
            float x = anchors[w * DD + k] * inv;
            s_an[w * DD + k] = x;
            g_anch[w * DD + k] = x;
        }
    }
    __syncthreads();
    if (w == 0) {
        float d00 = 0, d01 = 0, d02 = 0, d11 = 0, d12 = 0, d22 = 0;
        for (int k = lane; k < DD; k += 32) {
            float x0 = s_an[k], x1 = s_an[DD + k], x2 = s_an[2 * DD + k];
            d00 = fmaf(x0, x0, d00); d01 = fmaf(x0, x1, d01); d02 = fmaf(x0, x2, d02);
            d11 = fmaf(x1, x1, d11); d12 = fmaf(x1, x2, d12); d22 = fmaf(x2, x2, d22);
        }
        #pragma unroll
        for (int o = 16; o; o >>= 1) {
            d00 += __shfl_xor_sync(FULLMASK, d00, o);
            d01 += __shfl_xor_sync(FULLMASK, d01, o);
            d02 += __shfl_xor_sync(FULLMASK, d02, o);
            d11 += __shfl_xor_sync(FULLMASK, d11, o);
            d12 += __shfl_xor_sync(FULLMASK, d12, o);
            d22 += __shfl_xor_sync(FULLMASK, d22, o);
        }
        if (lane == 0) {
            g_G[0] = d00; g_G[1] = d01; g_G[2] = d02;
            g_G[3] = d11; g_G[4] = d12; g_G[5] = d22;
        }
    }
}

// ---------------------------------------------------------------------------
// main: 4 rows per warp-batch, anchors in registers, one chain per batch.
// ---------------------------------------------------------------------------
__global__ __launch_bounds__(128)
void liv_main(const float* __restrict__ h0,
              float* __restrict__ out_h,
              float* __restrict__ out_al,
              int B) {
    const int lane = threadIdx.x & 31;
    const int gw = (blockIdx.x * blockDim.x + threadIdx.x) >> 5;
    const int nwarps = (gridDim.x * blockDim.x) >> 5;

    // normalized anchors -> registers (L2-hot, coalesced)
    float4 A0[KPL], A1[KPL], A2[KPL];
    {
        const float4* av = (const float4*)g_anch;
        #pragma unroll
        for (int k = 0; k < KPL; k++) {
            A0[k] = av[k * 32 + lane];
            A1[k] = av[VV + k * 32 + lane];
            A2[k] = av[2 * VV + k * 32 + lane];
        }
    }
    const float G00 = g_G[0], G01 = g_G[1], G02 = g_G[2];
    const float G11 = g_G[3], G12 = g_G[4], G22 = g_G[5];

    const int nbatch = (B + RB - 1) / RB;

    for (int b = gw; b < nbatch; b += nwarps) {
        const int base = b * RB;

        // --- front-batched loads: 24 LDG.128 in flight ---
        float4 h[RB][KPL];
        #pragma unroll
        for (int j = 0; j < RB; j++) {
            int row = base + j; if (row >= B) row = B - 1;
            const float4* hp = (const float4*)h0 + (size_t)row * VV;
            #pragma unroll
            for (int k = 0; k < KPL; k++) h[j][k] = __ldg(hp + k * 32 + lane);
        }

        // --- per-row dots + reduce; park scalars in lane j ---
        float myN = 0.f, myT0 = 0.f, myT1 = 0.f, myT2 = 0.f;
        #pragma unroll
        for (int j = 0; j < RB; j++) {
            float N0 = 0.f, T0 = 0.f, T1 = 0.f, T2 = 0.f;
            #pragma unroll
            for (int k = 0; k < KPL; k++) {
                const float4 v = h[j][k];
                N0 = fmaf(v.x, v.x, N0);
                N0 = fmaf(v.y, v.y, N0);
                N0 = fmaf(v.z, v.z, N0);
                N0 = fmaf(v.w, v.w, N0);
                T0 = fmaf(v.x, A0[k].x, T0);
                T0 = fmaf(v.y, A0[k].y, T0);
                T0 = fmaf(v.z, A0[k].z, T0);
                T0 = fmaf(v.w, A0[k].w, T0);
                T1 = fmaf(v.x, A1[k].x, T1);
                T1 = fmaf(v.y, A1[k].y, T1);
                T1 = fmaf(v.z, A1[k].z, T1);
                T1 = fmaf(v.w, A1[k].w, T1);
                T2 = fmaf(v.x, A2[k].x, T2);
                T2 = fmaf(v.y, A2[k].y, T2);
                T2 = fmaf(v.z, A2[k].z, T2);
                T2 = fmaf(v.w, A2[k].w, T2);
            }
            #pragma unroll
            for (int o = 16; o; o >>= 1) {
                N0 += __shfl_xor_sync(FULLMASK, N0, o);
                T0 += __shfl_xor_sync(FULLMASK, T0, o);
                T1 += __shfl_xor_sync(FULLMASK, T1, o);
                T2 += __shfl_xor_sync(FULLMASK, T2, o);
            }
            if (lane == j) { myN = N0; myT0 = T0; myT1 = T1; myT2 = T2; }
        }

        // --- ONE branchless chain: lane j computes row base+j ---
        float p = 1.f, q0 = 0.f, q1 = 0.f, q2 = 0.f;
        float al0 = 0.f, al1 = 0.f, al2 = 0.f;
        const float KK = 28.853900817779268f;  // 20 * log2(e)
        #pragma unroll
        for (int s = 0; s < 7; s++) {
            float s0 = fmaf(p, myT0, fmaf(q0, G00, fmaf(q1, G01, q2 * G02)));
            float s1 = fmaf(p, myT1, fmaf(q0, G01, fmaf(q1, G11, q2 * G12)));
            float s2 = fmaf(p, myT2, fmaf(q0, G02, fmaf(q1, G12, q2 * G22)));
            float qT = fmaf(q0, myT0, fmaf(q1, myT1, q2 * myT2));
            float n2 = fmaf(p, fmaf(p, myN, qT),
                            fmaf(q0, s0, fmaf(q1, s1, q2 * s2)));
            float inv = rsqa(fmaxf(n2, 1e-24f));
            al0 = s0 * inv; al1 = s1 * inv; al2 = s2 * inv;
            if (s == 6) break;

            // softmax(20*al) without max-subtraction (|arg| <= ~29, safe)
            float e0 = ex2a(KK * al0);
            float e1 = ex2a(KK * al1);
            float e2 = ex2a(KK * al2);
            float invW = rcpa(e0 + e1 + e2);
            float w0 = e0 * invW, w1 = e1 * invW, w2 = e2 * invW;

            float c = fmaf(w0, al0, fmaf(w1, al1, w2 * al2));
            float beta = fmaf(-0.05f, c, 1.f);
            float n = n2 * inv;            // sqrt(n2)
            float delta = 0.05f * n;
            p *= beta;
            q0 = fmaf(beta, q0, delta * w0);
            q1 = fmaf(beta, q1, delta * w1);
            q2 = fmaf(beta, q2, delta * w2);

            // clip: ||h_new||^2 = n2*(1 + alpha^2*(||t||^2 - c^2)); branchless
            float t2 = fmaf(w0 * w0, G00,
                       fmaf(w1 * w1, G11,
                       fmaf(w2 * w2, G22,
                       2.f * fmaf(w0 * w1, G01,
                             fmaf(w0 * w2, G02, w1 * w2 * G12)))));
            float n2b = n2 * fmaf(0.0025f, t2 - c * c, 1.f);
            float g = fminf(1.f, 10.f * rsqa(n2b));
            p *= g; q0 *= g; q1 *= g; q2 *= g;
        }

        // --- outputs: broadcast (p,q) from lane j, write row base+j ---
        #pragma unroll
        for (int j = 0; j < RB; j++) {
            const int row = base + j;
            const float pj  = __shfl_sync(FULLMASK, p,  j);
            const float q0j = __shfl_sync(FULLMASK, q0, j);
            const float q1j = __shfl_sync(FULLMASK, q1, j);
            const float q2j = __shfl_sync(FULLMASK, q2, j);
            if (row < B) {
                float4* op = (float4*)out_h + (size_t)row * VV;
                #pragma unroll
                for (int k = 0; k < KPL; k++) {
                    float4 o;
                    o.x = fmaf(pj, h[j][k].x, fmaf(q0j, A0[k].x, fmaf(q1j, A1[k].x, q2j * A2[k].x)));
                    o.y = fmaf(pj, h[j][k].y, fmaf(q0j, A0[k].y, fmaf(q1j, A1[k].y, q2j * A2[k].y)));
                    o.z = fmaf(pj, h[j][k].z, fmaf(q0j, A0[k].z, fmaf(q1j, A1[k].z, q2j * A2[k].z)));
                    o.w = fmaf(pj, h[j][k].w, fmaf(q0j, A0[k].w, fmaf(q1j, A1[k].w, q2j * A2[k].w)));
                    op[k * 32 + lane] = o;
                }
            }
        }
        // alignments: lane j holds row base+j's values
        if (lane < RB && base + lane < B) {
            float* ap = out_al + (size_t)(base + lane) * 3;
            ap[0] = al0; ap[1] = al1; ap[2] = al2;
        }
    }
}

// ---------------------------------------------------------------------------
extern "C" void kernel_launch(void* const* d_in, const int* in_sizes, int n_in,
                              void* d_out, int out_size) {
    const float* h0 = (const float*)d_in[0];       // [B, 768]
    const float* anchors = (const float*)d_in[1];  // [3, 768]
    const int B = in_sizes[0] / DD;

    float* out_h = (float*)d_out;                    // [B, 768]
    float* out_al = (float*)d_out + (size_t)B * DD;  // [B, 3]

    liv_prep<<<1, 128>>>(anchors);

    const int threads = 128;              // 4 warps/block
    int nbatch = (B + RB - 1) / RB;       // 16384 batches of 4 rows
    int blocks = 1024;                    // 4096 warps -> 4 batches each
    int total_warps = blocks * (threads / 32);
    if (total_warps > nbatch) blocks = (nbatch + 3) / 4;
    liv_main<<<blocks, threads>>>(h0, out_h, out_al, B);
}